// round 15
// baseline (speedup 1.0000x reference)
#include <cuda_runtime.h>

#define DIMX   240
#define NTYPE  10
#define EPSV   1e-5f
#define MAXB   200704
#define RPB    256   // rows per reduce block
#define RU     4     // unroll (both paths)

__device__ float g_sum[NTYPE * 64];    // scalar-channel sums
__device__ float g_sq[NTYPE * DIMX];   // per-column sum of squares
__device__ int   g_cnti[NTYPE];
__device__ int   g_cursor[NTYPE];
__device__ int   g_perm[MAXB];

__global__ void k_zero() {
    int i = threadIdx.x;
    if (i < NTYPE) { g_cnti[i] = 0; g_cursor[i] = 0; }
}

__global__ void k_hist(const int* __restrict__ tp, int batch) {
    __shared__ int h[NTYPE];
    if (threadIdx.x < NTYPE) h[threadIdx.x] = 0;
    __syncthreads();
    for (int i = blockIdx.x * blockDim.x + threadIdx.x; i < batch;
         i += gridDim.x * blockDim.x) {
        atomicAdd(&h[tp[i]], 1);
    }
    __syncthreads();
    if (threadIdx.x < NTYPE) atomicAdd(&g_cnti[threadIdx.x], h[threadIdx.x]);
}

// Counting-sort scatter (inline 10-element scan of g_cnti). Its first blocks
// also zero the g_sq/g_sum accumulators (must be done before k_reduce, which
// is guaranteed by stream ordering).
__global__ void k_scatter(const int* __restrict__ tp, int batch) {
    __shared__ int h[NTYPE], base[NTYPE], soff[NTYPE];
    const int gi = blockIdx.x * blockDim.x + threadIdx.x;
    if (gi < NTYPE * DIMX) g_sq[gi] = 0.0f;
    if (gi < NTYPE * 64) g_sum[gi] = 0.0f;
    if (threadIdx.x < NTYPE) {
        h[threadIdx.x] = 0;
        int o = 0;
        for (int k = 0; k < threadIdx.x; k++) o += g_cnti[k];
        soff[threadIdx.x] = o;
    }
    __syncthreads();
    int t = 0, loc = 0;
    if (gi < batch) {
        t = tp[gi];
        loc = atomicAdd(&h[t], 1);
    }
    __syncthreads();
    if (threadIdx.x < NTYPE && h[threadIdx.x] > 0)
        base[threadIdx.x] = soff[threadIdx.x] + atomicAdd(&g_cursor[threadIdx.x], h[threadIdx.x]);
    __syncthreads();
    if (gi < batch) g_perm[base[t] + loc] = gi;
}

__device__ __forceinline__ void flush_acc(int t, int q, bool sc,
                                          float* ssq, float* ssm) {
    float* gq = g_sq + t * DIMX + q * 4;
    atomicAdd(gq + 0, ssq[0]);
    atomicAdd(gq + 1, ssq[1]);
    atomicAdd(gq + 2, ssq[2]);
    atomicAdd(gq + 3, ssq[3]);
    ssq[0] = ssq[1] = ssq[2] = ssq[3] = 0.f;
    if (sc) {
        float* gs = g_sum + t * 64 + q * 4;
        atomicAdd(gs + 0, ssm[0]);
        atomicAdd(gs + 1, ssm[1]);
        atomicAdd(gs + 2, ssm[2]);
        atomicAdd(gs + 3, ssm[3]);
        ssm[0] = ssm[1] = ssm[2] = ssm[3] = 0.f;
    }
}

// float4 reduce over bucket-sorted rows. Tile = 4 rows; thread (r,q) owns
// float4 q of row r. __launch_bounds__(256,6) -> <=42 regs -> 6 blocks/SM
// -> 888 resident slots >= grid 782 -> SINGLE WAVE, no tail.
__global__ void __launch_bounds__(256, 6)
k_reduce(const float4* __restrict__ x4, int batch) {
    __shared__ int soff[NTYPE + 1];
    __shared__ int sperm[RPB];
    const int tid = threadIdx.x;
    if (tid < NTYPE) {
        int o = 0;
        for (int k = 0; k < tid; k++) o += g_cnti[k];
        soff[tid] = o;
    }
    if (tid == NTYPE) soff[NTYPE] = batch;
    const int row0 = blockIdx.x * RPB;
    const int nrows = min(RPB, batch - row0);
    for (int j = tid; j < nrows; j += 256) sperm[j] = g_perm[row0 + j];
    __syncthreads();
    if (tid >= 240) return;

    const int r = tid / 60;
    const int q = tid - r * 60;
    const bool sc = (q < 16);   // scalar quad (cols 0..63)

    int tA = 0;
    while (row0 >= soff[tA + 1]) tA++;
    int tB = tA;
    while (row0 + nrows - 1 >= soff[tB + 1]) tB++;

    float ssq[4] = {0.f, 0.f, 0.f, 0.f};
    float ssm[4] = {0.f, 0.f, 0.f, 0.f};

    if (tA == tB && nrows == RPB) {
        // ---- fast path: single type, full block ----
#pragma unroll 1
        for (int j0 = 0; j0 < RPB / 4; j0 += RU) {
            float4 v[RU];
#pragma unroll
            for (int u = 0; u < RU; u++) {
                const unsigned row = (unsigned)sperm[(j0 + u) * 4 + r];
                v[u] = x4[row * 60u + (unsigned)q];
            }
#pragma unroll
            for (int u = 0; u < RU; u++) {
                ssq[0] = fmaf(v[u].x, v[u].x, ssq[0]);
                ssq[1] = fmaf(v[u].y, v[u].y, ssq[1]);
                ssq[2] = fmaf(v[u].z, v[u].z, ssq[2]);
                ssq[3] = fmaf(v[u].w, v[u].w, ssq[3]);
                if (sc) {
                    ssm[0] += v[u].x;
                    ssm[1] += v[u].y;
                    ssm[2] += v[u].z;
                    ssm[3] += v[u].w;
                }
            }
        }
        flush_acc(tA, q, sc, ssq, ssm);
        return;
    }

    // ---- slow path: boundary or partial block ----
    const int p0 = row0 + r;
    if (p0 >= batch) return;
    int curt = tA;
    while (p0 >= soff[curt + 1]) curt++;

    for (int tb = 0; tb < RPB / 4; tb += RU) {
        float4 v[RU];
        bool ok[RU];
#pragma unroll
        for (int u = 0; u < RU; u++) {
            const int j = (tb + u) * 4 + r;
            ok[u] = (j < nrows);
            if (ok[u]) {
                const unsigned row = (unsigned)sperm[j];
                v[u] = x4[row * 60u + (unsigned)q];
            }
        }
#pragma unroll
        for (int u = 0; u < RU; u++) {
            if (!ok[u]) continue;
            const int p = row0 + (tb + u) * 4 + r;
            if (p >= soff[curt + 1]) {
                flush_acc(curt, q, sc, ssq, ssm);
                while (p >= soff[curt + 1]) curt++;
            }
            ssq[0] = fmaf(v[u].x, v[u].x, ssq[0]);
            ssq[1] = fmaf(v[u].y, v[u].y, ssq[1]);
            ssq[2] = fmaf(v[u].z, v[u].z, ssq[2]);
            ssq[3] = fmaf(v[u].w, v[u].w, ssq[3]);
            if (sc) {
                ssm[0] += v[u].x;
                ssm[1] += v[u].y;
                ssm[2] += v[u].z;
                ssm[3] += v[u].w;
            }
        }
    }
    flush_acc(curt, q, sc, ssq, ssm);
}

// out = x * A[type][col] + C[type][col]. Stats (A/C) computed in-block from
// the raw accumulators (k_stats folded in). 4-row tiles, U=4 unroll.
#define UAPP 4
__global__ void __launch_bounds__(240)
k_apply(const float4* __restrict__ x4, const int* __restrict__ tp,
        const float* __restrict__ w, const float* __restrict__ b,
        float4* __restrict__ o4, int batch) {
    __shared__ __align__(16) float sA[NTYPE * DIMX];
    __shared__ __align__(16) float sC[NTYPE * DIMX];
    const int tid = threadIdx.x;

    // Stats prologue: iteration k handles type k, column tid.
    const int c = tid;
#pragma unroll 1
    for (int t = 0; t < NTYPE; t++) {
        const float cnt = fmaxf((float)g_cnti[t], 1.0f);
        const float* sq = g_sq + t * DIMX;
        float A, C;
        if (c < 64) {
            const float fm  = g_sum[t * 64 + c] / cnt;
            const float var = sq[c] / cnt - fm * fm;
            const float s   = rsqrtf(var + EPSV) * w[t * 112 + c];
            A = s;
            C = b[t * 64 + c] - fm * s;
        } else if (c < 160) {
            const int m = (c - 64) / 3;
            const int base = 64 + 3 * m;
            const float fn = (sq[base] + sq[base + 1] + sq[base + 2]) / (3.0f * cnt);
            A = rsqrtf(fn + EPSV) * w[t * 112 + 64 + m];
            C = 0.0f;
        } else {
            const int m = (c - 160) / 5;
            const int base = 160 + 5 * m;
            const float fn = (sq[base] + sq[base + 1] + sq[base + 2] + sq[base + 3] + sq[base + 4])
                             / (5.0f * cnt);
            A = rsqrtf(fn + EPSV) * w[t * 112 + 96 + m];
            C = 0.0f;
        }
        sA[t * DIMX + c] = A;
        sC[t * DIMX + c] = C;
    }
    __syncthreads();

    const int r = tid / 60;
    const int q = tid - r * 60;
    const int ntiles = (batch + 3) >> 2;
    const int ngrp = (ntiles + UAPP - 1) / UAPP;

    for (int g = blockIdx.x; g < ngrp; g += gridDim.x) {
        const int tile0 = g * UAPP;
        float4 xv[UAPP];
        int t[UAPP];
        bool ok[UAPP];
#pragma unroll
        for (int u = 0; u < UAPP; u++) {
            const int tile = tile0 + u;
            const int row = tile * 4 + r;
            ok[u] = (row < batch);
            if (ok[u]) {
                xv[u] = x4[(unsigned)tile * 240u + (unsigned)tid];
                t[u] = __ldg(tp + row);
            }
        }
#pragma unroll
        for (int u = 0; u < UAPP; u++) {
            if (ok[u]) {
                const int tile = tile0 + u;
                const float4 a  = *((const float4*)(sA + t[u] * DIMX) + q);
                const float4 cc = *((const float4*)(sC + t[u] * DIMX) + q);
                float4 res;
                res.x = fmaf(xv[u].x, a.x, cc.x);
                res.y = fmaf(xv[u].y, a.y, cc.y);
                res.z = fmaf(xv[u].z, a.z, cc.z);
                res.w = fmaf(xv[u].w, a.w, cc.w);
                o4[(unsigned)tile * 240u + (unsigned)tid] = res;
            }
        }
    }
}

extern "C" void kernel_launch(void* const* d_in, const int* in_sizes, int n_in,
                              void* d_out, int out_size) {
    const float* x  = (const float*)d_in[0];
    const int*   tp = (const int*)d_in[1];
    const float* w  = (const float*)d_in[2];
    const float* b  = (const float*)d_in[3];
    float* out = (float*)d_out;
    const int batch = in_sizes[1];

    k_zero<<<1, 32>>>();
    k_hist<<<296, 256>>>(tp, batch);
    k_scatter<<<(batch + 255) / 256, 256>>>(tp, batch);
    k_reduce<<<(batch + RPB - 1) / RPB, 256>>>((const float4*)x, batch);
    k_apply<<<592, 240>>>((const float4*)x, tp, w, b, (float4*)out, batch);
}